// round 5
// baseline (speedup 1.0000x reference)
#include <cuda_runtime.h>

// Problem constants: H=51, L=3, IN=2, B=1024, T=2048
#define Hh    51
#define Gg    204     // 4*H
#define Tt    2048
#define NTH   512
#define NCTA  128     // 1024 / 8 batches per CTA

// Fused state vector (per batch), element indices:
//   0..1 x | 2..52 h0 | 53 one(bias c0,c1) | 54..104 h1 | 105 one(bias c2)
//   106..156 h2 | 157..159 pad
// Pair-packed: vbuf[(e>>1)*16 + b*2 + (e&1)], 80 pairs.
// Weights col-major pair-packed: w[kp*408 + row*2 + par], bias folded.
#define W0_PAIRS  27     // cell0: e0..53
#define W12_PAIRS 52     // cell1: e2..105, cell2: e54..157

#define OFF_W0    0
#define OFF_W1    (OFF_W0 + W0_PAIRS*408)    // 11016
#define OFF_W2    (OFF_W1 + W12_PAIRS*408)   // 32232
#define OFF_VBUF  (OFF_W2 + W12_PAIRS*408)   // 53448 : 80*16 = 1280
#define OFF_CBUF  (OFF_VBUF + 1280)          // 3*408 = 1224
#define OFF_GATES (OFF_CBUF + 1224)          // 204*8 = 1632
#define OFF_WLIN  (OFF_GATES + 1632)         // 102
#define OFF_BLIN  (OFF_WLIN + 102)           // 2
#define SM_FLOATS (OFF_BLIN + 2)             // 57688
#define SM_BYTES  (SM_FLOATS * 4)            // 230752 <= 232448

typedef unsigned long long ull;

__device__ __forceinline__ float sigm_f(float x) {
    return __fdividef(1.0f, 1.0f + __expf(-x));
}
__device__ __forceinline__ float tanh_f(float x) {
    return 1.0f - __fdividef(2.0f, __expf(2.0f * x) + 1.0f);
}
__device__ __forceinline__ ull fma2(ull a, ull b, ull c) {
    ull d;
    asm("fma.rn.f32x2 %0, %1, %2, %3;" : "=l"(d) : "l"(a), "l"(b), "l"(c));
    return d;
}
__device__ __forceinline__ float red2(ull a) {
    float lo, hi;
    asm("mov.b64 {%0, %1}, %2;" : "=f"(lo), "=f"(hi) : "l"(a));
    return lo + hi;
}

// Thread (rp, bp): gate rows 2rp,2rp+1 x batches 2bp,2bp+1, full k.
// Inner loop: 2x LDS.128 + 4x fma2 per k-pair. Warp-uniform kp => 2 phases/kp.
template<int P>
__device__ __forceinline__ void matvec4(int rp, int bp,
    const float* __restrict__ wcol, const float* __restrict__ vb,
    float* __restrict__ gates)
{
    ull a00 = 0ull, a01 = 0ull, a10 = 0ull, a11 = 0ull;
    const float* wp = wcol + rp * 4;
    const float* vp = vb + bp * 4;
#pragma unroll
    for (int kp = 0; kp < P; kp++) {
        ulonglong2 w = *(const ulonglong2*)(wp + kp * 408);  // rows 2rp,2rp+1 (k_e,k_o)
        ulonglong2 v = *(const ulonglong2*)(vp + kp * 16);   // batches 2bp,2bp+1 (k_e,k_o)
        a00 = fma2(w.x, v.x, a00);
        a01 = fma2(w.x, v.y, a01);
        a10 = fma2(w.y, v.x, a10);
        a11 = fma2(w.y, v.y, a11);
    }
    *(float2*)(gates + (2*rp)   * 8 + 2*bp) = make_float2(red2(a00), red2(a01));
    *(float2*)(gates + (2*rp+1) * 8 + 2*bp) = make_float2(red2(a10), red2(a11));
}

__device__ __forceinline__ void cellup(int el, const float* __restrict__ gates,
                                       float* __restrict__ c, float* __restrict__ vbuf,
                                       int base_e)
{
    float gi = gates[el], gf = gates[408 + el], gg = gates[816 + el], go = gates[1224 + el];
    float cn = sigm_f(gf) * c[el] + sigm_f(gi) * tanh_f(gg);
    c[el] = cn;
    int jj = el >> 3, b = el & 7, e = base_e + jj;
    vbuf[(e >> 1) * 16 + 2 * b + (e & 1)] = sigm_f(go) * tanh_f(cn);
}

__device__ __forceinline__ void head_out(int hid, const float* __restrict__ vbuf,
                                         const float* __restrict__ wlin,
                                         const float* __restrict__ blin,
                                         float* __restrict__ out, int b0g, int t)
{
    int b = hid >> 1, o = hid & 1;
    float z = blin[o];
#pragma unroll
    for (int k = 0; k < Hh; k++) {
        int e = 106 + k;
        z = fmaf(wlin[o * Hh + k], vbuf[(e >> 1) * 16 + 2 * b + (e & 1)], z);
    }
    if (o == 1) z = (z > 30.0f) ? z : log1pf(__expf(z));
    out[(size_t)(b0g + b) * (Tt * 2) + (size_t)t * 2 + o] = z;
}

__global__ void __launch_bounds__(NTH, 1) lstm_persistent_kernel(
    const float* __restrict__ g_input, const float* __restrict__ g_time,
    const float* __restrict__ Wih0, const float* __restrict__ Whh0,
    const float* __restrict__ bih0, const float* __restrict__ bhh0,
    const float* __restrict__ Wih1, const float* __restrict__ Whh1,
    const float* __restrict__ bih1, const float* __restrict__ bhh1,
    const float* __restrict__ Wih2, const float* __restrict__ Whh2,
    const float* __restrict__ bih2, const float* __restrict__ bhh2,
    const float* __restrict__ Wlin, const float* __restrict__ blin_g,
    float* __restrict__ out)
{
    extern __shared__ float sm[];
    float* w0    = sm + OFF_W0;
    float* w1    = sm + OFF_W1;
    float* w2    = sm + OFF_W2;
    float* vbuf  = sm + OFF_VBUF;
    float* cbuf  = sm + OFF_CBUF;
    float* gates = sm + OFF_GATES;
    float* wlin  = sm + OFF_WLIN;
    float* blin  = sm + OFF_BLIN;

    const int tid = threadIdx.x;
    const int b0g = blockIdx.x * 8;

    // ---- build column-major pair-packed weights (bias folded at one-slots) ----
    for (int i = tid; i < Gg * 54; i += NTH) {
        int r = i / 54, e = i % 54;
        float v;
        if (e < 2)       v = Wih0[r * 2 + e];
        else if (e < 53) v = Whh0[r * Hh + (e - 2)];
        else             v = bih0[r] + bhh0[r];
        w0[(e >> 1) * 408 + r * 2 + (e & 1)] = v;
    }
    for (int i = tid; i < Gg * 104; i += NTH) {
        int r = i / 104, e = i % 104;   // fused el for cell1 = e+2, cell2 = e+54
        float a, b;
        if (e < 51)       { a = Wih1[r * Hh + e];        b = Wih2[r * Hh + e]; }
        else if (e == 51) { a = bih1[r] + bhh1[r];       b = bih2[r] + bhh2[r]; }
        else if (e < 103) { a = Whh1[r * Hh + (e - 52)]; b = Whh2[r * Hh + (e - 52)]; }
        else              { a = 0.0f;                    b = 0.0f; }
        int off = (e >> 1) * 408 + r * 2 + (e & 1);
        w1[off] = a; w2[off] = b;
    }
    if (tid < 102) wlin[tid] = Wlin[tid];
    if (tid < 2)   blin[tid] = blin_g[tid];
    for (int i = tid; i < 1280; i += NTH) vbuf[i] = 0.0f;
    for (int i = tid; i < 1224; i += NTH) cbuf[i] = 0.0f;
    __syncthreads();
    if (tid < 8) {
        vbuf[26 * 16 + tid * 2 + 1] = 1.0f;   // e53  = 1.0 (bias cells 0,1)
        vbuf[52 * 16 + tid * 2 + 1] = 1.0f;   // e105 = 1.0 (bias cell 2)
    }
    // initial x(0): 16 threads, one scalar each
    if (tid >= 464 && tid < 480) {
        int l = tid - 464, b = l >> 1, f = l & 1;
        const float* src = f ? g_time : g_input;
        vbuf[2 * b + f] = src[(size_t)(b0g + b) * Tt];   // pair 0, e = f
    }
    __syncthreads();

    float* c0 = cbuf;
    float* c1 = cbuf + 408;
    float* c2 = cbuf + 816;

    const int rp = tid >> 2;      // 0..101 (valid when tid < 408)
    const int bp = tid & 3;
    const bool mv = (tid < 408);

    float px = 0.0f;              // prefetched x element (threads 464..479)

    for (int t = 0; t < Tt; t++) {
        // ---- phase A: cell0 matvec || head(t-1) ----
        if (mv) matvec4<W0_PAIRS>(rp, bp, w0, vbuf, gates);
        else if (tid >= 448 && tid < 464) {
            if (t > 0) head_out(tid - 448, vbuf, wlin, blin, out, b0g, t - 1);
        }
        __syncthreads();
        if (mv) cellup(tid, gates, c0, vbuf, 2);
        __syncthreads();

        // ---- phase B: cell1 matvec || prefetch x(t+1) into regs ----
        if (mv) matvec4<W12_PAIRS>(rp, bp, w1, vbuf + 16, gates);
        else if (tid >= 464 && tid < 480 && (t + 1) < Tt) {
            int l = tid - 464, b = l >> 1, f = l & 1;
            const float* src = f ? g_time : g_input;
            px = src[(size_t)(b0g + b) * Tt + (t + 1)];
        }
        __syncthreads();
        if (mv) cellup(tid, gates, c1, vbuf, 54);
        __syncthreads();

        // ---- phase C: cell2 matvec || commit x(t+1) into vbuf pair 0 ----
        if (mv) matvec4<W12_PAIRS>(rp, bp, w2, vbuf + 27 * 16, gates);
        else if (tid >= 464 && tid < 480 && (t + 1) < Tt) {
            int l = tid - 464, b = l >> 1, f = l & 1;
            vbuf[2 * b + f] = px;
        }
        __syncthreads();
        if (mv) cellup(tid, gates, c2, vbuf, 106);
        __syncthreads();
    }

    // final head for t = Tt-1
    if (tid >= 448 && tid < 464)
        head_out(tid - 448, vbuf, wlin, blin, out, b0g, Tt - 1);
}

extern "C" void kernel_launch(void* const* d_in, const int* in_sizes, int n_in,
                              void* d_out, int out_size)
{
    const float* input = (const float*)d_in[0];
    const float* timei = (const float*)d_in[1];
    const float* Wih0  = (const float*)d_in[2];
    const float* Whh0  = (const float*)d_in[3];
    const float* bih0  = (const float*)d_in[4];
    const float* bhh0  = (const float*)d_in[5];
    const float* Wih1  = (const float*)d_in[6];
    const float* Whh1  = (const float*)d_in[7];
    const float* bih1  = (const float*)d_in[8];
    const float* bhh1  = (const float*)d_in[9];
    const float* Wih2  = (const float*)d_in[10];
    const float* Whh2  = (const float*)d_in[11];
    const float* bih2  = (const float*)d_in[12];
    const float* bhh2  = (const float*)d_in[13];
    const float* Wlin  = (const float*)d_in[14];
    const float* blin  = (const float*)d_in[15];
    float* out = (float*)d_out;

    cudaFuncSetAttribute(lstm_persistent_kernel,
                         cudaFuncAttributeMaxDynamicSharedMemorySize, SM_BYTES);

    lstm_persistent_kernel<<<NCTA, NTH, SM_BYTES>>>(
        input, timei,
        Wih0, Whh0, bih0, bhh0,
        Wih1, Whh1, bih1, bhh1,
        Wih2, Whh2, bih2, bhh2,
        Wlin, blin, out);
}